// round 1
// baseline (speedup 1.0000x reference)
#include <cuda_runtime.h>
#include <math.h>

#define BATCH 2
#define SEQN 2048
#define EMB 1024
#define NH 16
#define HD 64
#define NB 32              // sequence blocks of 64
#define MROWS (BATCH*SEQN) // 4096
#define SSTRIDE 68         // smem row stride (floats): odd*4 -> conflict-free + float4-aligned

// ---------------- scratch (static device globals; no allocation) ----------------
__device__ float g_q[BATCH*SEQN*EMB];
__device__ float g_k[BATCH*SEQN*EMB];
__device__ float g_v[BATCH*SEQN*EMB];
__device__ float g_ctx[BATCH*SEQN*EMB];
__device__ unsigned g_blockmask[NB];

// ---------------- packed f32x2 helpers ----------------
typedef unsigned long long u64;
__device__ __forceinline__ u64 pack2(float x, float y) {
    u64 r; asm("mov.b64 %0, {%1,%2};" : "=l"(r) : "f"(x), "f"(y)); return r;
}
__device__ __forceinline__ void unpack2(u64 v, float& x, float& y) {
    asm("mov.b64 {%0,%1}, %2;" : "=f"(x), "=f"(y) : "l"(v));
}
__device__ __forceinline__ u64 ffma2(u64 a, u64 b, u64 c) {
    u64 d; asm("fma.rn.f32x2 %0, %1, %2, %3;" : "=l"(d) : "l"(a), "l"(b), "l"(c)); return d;
}

// ---------------- MT19937 mask init (replicates np.random.RandomState(0)) ----------------
__global__ void init_mask_kernel() {
    if (threadIdx.x != 0 || blockIdx.x != 0) return;
    unsigned mt[624];
    int mti;
    // init_genrand(0): numpy legacy scalar-int seeding
    {
        unsigned s = 0u;
        for (int i = 0; i < 624; ++i) {
            mt[i] = s;
            s = 1812433253u * (s ^ (s >> 30)) + (unsigned)i + 1u;
        }
        mti = 624;
    }
    auto next32 = [&]() -> unsigned {
        if (mti >= 624) {
            for (int i = 0; i < 624; ++i) {
                unsigned y = (mt[i] & 0x80000000u) | (mt[(i + 1) % 624] & 0x7fffffffu);
                unsigned v = mt[(i + 397) % 624] ^ (y >> 1);
                if (y & 1u) v ^= 0x9908b0dfu;
                mt[i] = v;
            }
            mti = 0;
        }
        unsigned y = mt[mti++];
        y ^= y >> 11;
        y ^= (y << 7) & 0x9d2c5680u;
        y ^= (y << 15) & 0xefc60000u;
        y ^= y >> 18;
        return y;
    };
    auto rand_interval = [&](unsigned maxv) -> unsigned {
        // numpy random_interval: masked rejection on 32-bit draws (maxv < 2^32)
        if (maxv == 0u) return 0u;
        unsigned mask = maxv;
        mask |= mask >> 1; mask |= mask >> 2; mask |= mask >> 4;
        mask |= mask >> 8; mask |= mask >> 16;
        unsigned v;
        do { v = next32() & mask; } while (v > maxv);
        return v;
    };

    unsigned bm[NB];
    // global row block 0 attends everything
    bm[0] = 0xffffffffu;
    for (int qb = 1; qb < NB; ++qb) {
        unsigned m = 1u; // global column block 0
        int lo = qb - 3; if (lo < 0) lo = 0;
        int hi = qb + 3; if (hi > NB - 1) hi = NB - 1;
        for (int kb = lo; kb <= hi; ++kb) m |= (1u << kb); // sliding window
        bm[qb] = m;
    }
    // random blocks, exact RNG order: b = 1..31
    for (int b = 1; b < NB; ++b) {
        int avail[NB]; int pop = 0;
        for (int x = 1; x < NB; ++x)
            if ((x - b > 3) || (b - x > 3)) avail[pop++] = x;
        if (pop == 0) continue;
        int perm[NB];
        for (int i = 0; i < pop; ++i) perm[i] = i;
        for (int i = pop - 1; i > 0; --i) {
            unsigned j = rand_interval((unsigned)i);
            int tmp = perm[i]; perm[i] = perm[j]; perm[j] = tmp;
        }
        int take = pop < 3 ? pop : 3;
        for (int tsel = 0; tsel < take; ++tsel)
            bm[b] |= (1u << avail[perm[tsel]]);
    }
    for (int i = 0; i < NB; ++i) g_blockmask[i] = bm[i];
}

// ---------------- SGEMM: C[M,N] = A[M,K] @ W[N,K]^T + bias[N] ----------------
// 128x128 tile, 256 threads, 8x8 microtile, f32x2-packed FMAs (row pairs).
__global__ __launch_bounds__(256) void sgemm_nt_bias(
    const float* __restrict__ A, const float* __restrict__ W,
    const float* __restrict__ bias, float* __restrict__ C,
    int M, int N, int K)
{
    __shared__ float As[8][128];
    __shared__ float Bs[8][128];
    const int t = threadIdx.x;
    const int m0 = blockIdx.y * 128;
    const int n0 = blockIdx.x * 128;
    const int tx = t & 15, ty = t >> 4;
    const int lrow = t >> 1;
    const int lc4 = (t & 1) * 4;

    u64 acc[4][8];
#pragma unroll
    for (int i = 0; i < 4; ++i)
#pragma unroll
        for (int j = 0; j < 8; ++j) acc[i][j] = 0ull;

    const float* aptr = A + (size_t)(m0 + lrow) * K + lc4;
    const float* wptr = W + (size_t)(n0 + lrow) * K + lc4;

    for (int k0 = 0; k0 < K; k0 += 8) {
        float4 av = *(const float4*)(aptr + k0);
        float4 wv = *(const float4*)(wptr + k0);
        __syncthreads();
        As[lc4 + 0][lrow] = av.x; As[lc4 + 1][lrow] = av.y;
        As[lc4 + 2][lrow] = av.z; As[lc4 + 3][lrow] = av.w;
        Bs[lc4 + 0][lrow] = wv.x; Bs[lc4 + 1][lrow] = wv.y;
        Bs[lc4 + 2][lrow] = wv.z; Bs[lc4 + 3][lrow] = wv.w;
        __syncthreads();
#pragma unroll
        for (int kk = 0; kk < 8; ++kk) {
            const u64* ap0 = (const u64*)&As[kk][ty * 4];
            const u64* ap1 = (const u64*)&As[kk][64 + ty * 4];
            u64 aa[4];
            aa[0] = ap0[0]; aa[1] = ap0[1];
            aa[2] = ap1[0]; aa[3] = ap1[1];
            float4 b0 = *(const float4*)&Bs[kk][tx * 4];
            float4 b1 = *(const float4*)&Bs[kk][64 + tx * 4];
            u64 bb[8];
            bb[0] = pack2(b0.x, b0.x); bb[1] = pack2(b0.y, b0.y);
            bb[2] = pack2(b0.z, b0.z); bb[3] = pack2(b0.w, b0.w);
            bb[4] = pack2(b1.x, b1.x); bb[5] = pack2(b1.y, b1.y);
            bb[6] = pack2(b1.z, b1.z); bb[7] = pack2(b1.w, b1.w);
#pragma unroll
            for (int i = 0; i < 4; ++i)
#pragma unroll
                for (int j = 0; j < 8; ++j)
                    acc[i][j] = ffma2(aa[i], bb[j], acc[i][j]);
        }
    }

    // epilogue: acc[i] holds row pair; i=0:(ty*4,ty*4+1) i=1:(ty*4+2,+3) i=2/3: +64
#pragma unroll
    for (int p = 0; p < 4; ++p) {
        int mr = m0 + ((p < 2) ? (ty * 4 + 2 * p) : (64 + ty * 4 + 2 * (p - 2)));
#pragma unroll
        for (int j = 0; j < 8; ++j) {
            int n = n0 + ((j < 4) ? (tx * 4 + j) : (64 + tx * 4 + (j - 4)));
            float lo, hi;
            unpack2(acc[p][j], lo, hi);
            float bv = bias[n];
            C[(size_t)mr * N + n]       = lo + bv;
            C[(size_t)(mr + 1) * N + n] = hi + bv;
        }
    }
}

// ---------------- Block-sparse flash attention ----------------
// Grid: (qb=32, b*H=32). 256 threads. Each thread: rows {q2, q2+32}, d-range [c*8, c*8+8).
__global__ __launch_bounds__(256) void bigbird_attn(
    const float* __restrict__ Q, const float* __restrict__ K,
    const float* __restrict__ V, float* __restrict__ O)
{
    extern __shared__ float smem[];
    float* sQ = smem;
    float* sK = smem + 64 * SSTRIDE;
    float* sV = smem + 2 * 64 * SSTRIDE;

    const int t = threadIdx.x;
    const int qb = blockIdx.x;
    const int b = blockIdx.y >> 4;
    const int h = blockIdx.y & 15;
    const size_t base = (size_t)b * SEQN * EMB + (size_t)h * HD;

    // load Q tile (64x64)
    {
        const float* src = Q + base + (size_t)qb * 64 * EMB;
#pragma unroll
        for (int it = 0; it < 4; ++it) {
            int lin = t + 256 * it;
            int row = lin >> 4, c4 = (lin & 15) * 4;
            *(float4*)(sQ + row * SSTRIDE + c4) = *(const float4*)(src + (size_t)row * EMB + c4);
        }
    }

    const int c = t & 7;
    const int q2 = t >> 3;
    float m0 = -INFINITY, m1 = -INFINITY, l0 = 0.f, l1 = 0.f;
    float acc0[8], acc1[8];
#pragma unroll
    for (int j = 0; j < 8; ++j) { acc0[j] = 0.f; acc1[j] = 0.f; }

    const unsigned bmask = g_blockmask[qb];

    for (int kb = 0; kb < NB; ++kb) {
        if (!((bmask >> kb) & 1u)) continue;
        __syncthreads();
        {
            const float* ks = K + base + (size_t)kb * 64 * EMB;
            const float* vs = V + base + (size_t)kb * 64 * EMB;
#pragma unroll
            for (int it = 0; it < 4; ++it) {
                int lin = t + 256 * it;
                int row = lin >> 4, c4 = (lin & 15) * 4;
                *(float4*)(sK + row * SSTRIDE + c4) = *(const float4*)(ks + (size_t)row * EMB + c4);
                *(float4*)(sV + row * SSTRIDE + c4) = *(const float4*)(vs + (size_t)row * EMB + c4);
            }
        }
        __syncthreads();

        // scores: thread computes S[q2][8kk+c], S[q2+32][8kk+c]
        float s0[8], s1[8];
#pragma unroll
        for (int kk = 0; kk < 8; ++kk) { s0[kk] = 0.f; s1[kk] = 0.f; }
        const float* qr0 = sQ + q2 * SSTRIDE;
        const float* qr1 = sQ + (q2 + 32) * SSTRIDE;
#pragma unroll 4
        for (int d = 0; d < 64; ++d) {
            float qv0 = qr0[d], qv1 = qr1[d];
#pragma unroll
            for (int kk = 0; kk < 8; ++kk) {
                float kv = sK[(8 * kk + c) * SSTRIDE + d];
                s0[kk] = fmaf(qv0, kv, s0[kk]);
                s1[kk] = fmaf(qv1, kv, s1[kk]);
            }
        }

        // online softmax update (width-8 shuffle groups share one query row)
        float rmax0 = -INFINITY, rmax1 = -INFINITY;
#pragma unroll
        for (int kk = 0; kk < 8; ++kk) {
            s0[kk] *= 0.125f; s1[kk] *= 0.125f;
            rmax0 = fmaxf(rmax0, s0[kk]); rmax1 = fmaxf(rmax1, s1[kk]);
        }
#pragma unroll
        for (int off = 1; off < 8; off <<= 1) {
            rmax0 = fmaxf(rmax0, __shfl_xor_sync(0xffffffffu, rmax0, off, 8));
            rmax1 = fmaxf(rmax1, __shfl_xor_sync(0xffffffffu, rmax1, off, 8));
        }
        float mn0 = fmaxf(m0, rmax0), mn1 = fmaxf(m1, rmax1);
        float al0 = expf(m0 - mn0), al1 = expf(m1 - mn1);
        float sum0 = 0.f, sum1 = 0.f;
#pragma unroll
        for (int kk = 0; kk < 8; ++kk) {
            s0[kk] = expf(s0[kk] - mn0); sum0 += s0[kk];
            s1[kk] = expf(s1[kk] - mn1); sum1 += s1[kk];
        }
#pragma unroll
        for (int off = 1; off < 8; off <<= 1) {
            sum0 += __shfl_xor_sync(0xffffffffu, sum0, off, 8);
            sum1 += __shfl_xor_sync(0xffffffffu, sum1, off, 8);
        }
        l0 = l0 * al0 + sum0; l1 = l1 * al1 + sum1;
        m0 = mn0; m1 = mn1;
#pragma unroll
        for (int j = 0; j < 8; ++j) { acc0[j] *= al0; acc1[j] *= al1; }

        // acc += P @ V : P row elements fetched from lane owners via width-8 shuffle
#pragma unroll
        for (int kk = 0; kk < 8; ++kk) {
#pragma unroll
            for (int cc = 0; cc < 8; ++cc) {
                float pv0 = __shfl_sync(0xffffffffu, s0[kk], cc, 8);
                float pv1 = __shfl_sync(0xffffffffu, s1[kk], cc, 8);
                const float* vr = sV + (8 * kk + cc) * SSTRIDE + c * 8;
                float4 va = *(const float4*)vr;
                float4 vb = *(const float4*)(vr + 4);
                acc0[0] = fmaf(pv0, va.x, acc0[0]); acc0[1] = fmaf(pv0, va.y, acc0[1]);
                acc0[2] = fmaf(pv0, va.z, acc0[2]); acc0[3] = fmaf(pv0, va.w, acc0[3]);
                acc0[4] = fmaf(pv0, vb.x, acc0[4]); acc0[5] = fmaf(pv0, vb.y, acc0[5]);
                acc0[6] = fmaf(pv0, vb.z, acc0[6]); acc0[7] = fmaf(pv0, vb.w, acc0[7]);
                acc1[0] = fmaf(pv1, va.x, acc1[0]); acc1[1] = fmaf(pv1, va.y, acc1[1]);
                acc1[2] = fmaf(pv1, va.z, acc1[2]); acc1[3] = fmaf(pv1, va.w, acc1[3]);
                acc1[4] = fmaf(pv1, vb.x, acc1[4]); acc1[5] = fmaf(pv1, vb.y, acc1[5]);
                acc1[6] = fmaf(pv1, vb.z, acc1[6]); acc1[7] = fmaf(pv1, vb.w, acc1[7]);
            }
        }
    }

    const float inv0 = 1.f / l0, inv1 = 1.f / l1;
    float* o0 = O + base + (size_t)(qb * 64 + q2) * EMB + c * 8;
    float* o1 = O + base + (size_t)(qb * 64 + q2 + 32) * EMB + c * 8;
    float4 w0a = make_float4(acc0[0] * inv0, acc0[1] * inv0, acc0[2] * inv0, acc0[3] * inv0);
    float4 w0b = make_float4(acc0[4] * inv0, acc0[5] * inv0, acc0[6] * inv0, acc0[7] * inv0);
    float4 w1a = make_float4(acc1[0] * inv1, acc1[1] * inv1, acc1[2] * inv1, acc1[3] * inv1);
    float4 w1b = make_float4(acc1[4] * inv1, acc1[5] * inv1, acc1[6] * inv1, acc1[7] * inv1);
    *(float4*)(o0)     = w0a;
    *(float4*)(o0 + 4) = w0b;
    *(float4*)(o1)     = w1a;
    *(float4*)(o1 + 4) = w1b;
}

// ---------------- launcher ----------------
extern "C" void kernel_launch(void* const* d_in, const int* in_sizes, int n_in,
                              void* d_out, int out_size)
{
    (void)in_sizes; (void)n_in; (void)out_size;
    const float* hs = (const float*)d_in[0];
    const float* wq = (const float*)d_in[1];
    const float* bq = (const float*)d_in[2];
    const float* wk = (const float*)d_in[3];
    const float* bk = (const float*)d_in[4];
    const float* wv = (const float*)d_in[5];
    const float* bv = (const float*)d_in[6];
    const float* wo = (const float*)d_in[7];
    const float* bo = (const float*)d_in[8];
    float* out = (float*)d_out;

    float *q, *k, *v, *ctx;
    cudaGetSymbolAddress((void**)&q, g_q);
    cudaGetSymbolAddress((void**)&k, g_k);
    cudaGetSymbolAddress((void**)&v, g_v);
    cudaGetSymbolAddress((void**)&ctx, g_ctx);

    const int attn_smem = 3 * 64 * SSTRIDE * (int)sizeof(float); // 52224 B
    cudaFuncSetAttribute(bigbird_attn, cudaFuncAttributeMaxDynamicSharedMemorySize, attn_smem);

    init_mask_kernel<<<1, 1>>>();

    dim3 gproj(EMB / 128, MROWS / 128); // (8, 32)
    sgemm_nt_bias<<<gproj, 256>>>(hs, wq, bq, q, MROWS, EMB, EMB);
    sgemm_nt_bias<<<gproj, 256>>>(hs, wk, bk, k, MROWS, EMB, EMB);
    sgemm_nt_bias<<<gproj, 256>>>(hs, wv, bv, v, MROWS, EMB, EMB);

    bigbird_attn<<<dim3(NB, BATCH * NH), 256, attn_smem>>>(q, k, v, ctx);

    sgemm_nt_bias<<<gproj, 256>>>(ctx, wo, bo, out, MROWS, EMB, EMB);
}

// round 2
// speedup vs baseline: 2.7181x; 2.7181x over previous
#include <cuda_runtime.h>
#include <cuda_bf16.h>
#include <math.h>

typedef unsigned u32;
typedef unsigned long long u64;

#define BATCH 2
#define SEQN 2048
#define EMB 1024
#define NH 16
#define HD 64
#define NB 32
#define MROWS (BATCH*SEQN)   // 4096

// ---------------- scratch: static device globals ----------------
__device__ __nv_bfloat16 g_hs_h[MROWS*EMB], g_hs_l[MROWS*EMB];
__device__ __nv_bfloat16 g_wq_h[EMB*EMB], g_wq_l[EMB*EMB];
__device__ __nv_bfloat16 g_wk_h[EMB*EMB], g_wk_l[EMB*EMB];
__device__ __nv_bfloat16 g_wv_h[EMB*EMB], g_wv_l[EMB*EMB];
__device__ __nv_bfloat16 g_wo_h[EMB*EMB], g_wo_l[EMB*EMB];
__device__ __nv_bfloat16 g_q_h[MROWS*EMB], g_q_l[MROWS*EMB];
__device__ __nv_bfloat16 g_k_h[MROWS*EMB], g_k_l[MROWS*EMB];
__device__ __nv_bfloat16 g_v_h[MROWS*EMB], g_v_l[MROWS*EMB];
__device__ __nv_bfloat16 g_c_h[MROWS*EMB], g_c_l[MROWS*EMB];
__device__ unsigned g_blockmask[NB];

// ---------------- asm helpers ----------------
__device__ __forceinline__ u32 smem_u32(const void* p) {
    return (u32)__cvta_generic_to_shared(p);
}
__device__ __forceinline__ void ldsm4(u32 a[4], u32 addr) {
    asm volatile("ldmatrix.sync.aligned.m8n8.x4.shared.b16 {%0,%1,%2,%3}, [%4];"
        : "=r"(a[0]), "=r"(a[1]), "=r"(a[2]), "=r"(a[3]) : "r"(addr));
}
__device__ __forceinline__ void ldsm4t(u32 a[4], u32 addr) {
    asm volatile("ldmatrix.sync.aligned.m8n8.x4.trans.shared.b16 {%0,%1,%2,%3}, [%4];"
        : "=r"(a[0]), "=r"(a[1]), "=r"(a[2]), "=r"(a[3]) : "r"(addr));
}
__device__ __forceinline__ void mma16816(float d[4], const u32 a[4], u32 b0, u32 b1) {
    asm volatile("mma.sync.aligned.m16n8k16.row.col.f32.bf16.bf16.f32 "
        "{%0,%1,%2,%3},{%4,%5,%6,%7},{%8,%9},{%0,%1,%2,%3};"
        : "+f"(d[0]), "+f"(d[1]), "+f"(d[2]), "+f"(d[3])
        : "r"(a[0]), "r"(a[1]), "r"(a[2]), "r"(a[3]), "r"(b0), "r"(b1));
}
__device__ __forceinline__ void cpa16(u32 dst, const void* src) {
    asm volatile("cp.async.cg.shared.global [%0], [%1], 16;" :: "r"(dst), "l"(src));
}
#define CP_COMMIT asm volatile("cp.async.commit_group;" ::: "memory")
#define CP_WAIT0  asm volatile("cp.async.wait_group 0;" ::: "memory")
#define CP_WAIT1  asm volatile("cp.async.wait_group 1;" ::: "memory")

// swizzles: 64B-row tiles (GEMM, 32 bf16/row) and 128B-row tiles (attention, 64 bf16/row)
__device__ __forceinline__ u32 swzG(u32 off) { return off ^ (((off >> 7) & 3u) << 4); }
__device__ __forceinline__ u32 swzA(u32 off) { return off ^ ((off >> 3) & 0x70u); }

// split two fp32 into packed bf16 hi-pair and lo-pair (elem0 in low half)
__device__ __forceinline__ void split_pair(float x0, float x1, u32& h, u32& l) {
    __nv_bfloat16 h0 = __float2bfloat16(x0), h1 = __float2bfloat16(x1);
    float r0 = x0 - __bfloat162float(h0), r1 = x1 - __bfloat162float(h1);
    __nv_bfloat16 l0 = __float2bfloat16(r0), l1 = __float2bfloat16(r1);
    __nv_bfloat162 hp; hp.x = h0; hp.y = h1;
    __nv_bfloat162 lp; lp.x = l0; lp.y = l1;
    h = *reinterpret_cast<u32*>(&hp);
    l = *reinterpret_cast<u32*>(&lp);
}

// ---------------- MT19937 mask init (np.random.RandomState(0)) ----------------
__global__ void init_mask_kernel() {
    if (threadIdx.x != 0 || blockIdx.x != 0) return;
    unsigned mt[624]; int mti;
    {
        unsigned s = 0u;
        for (int i = 0; i < 624; ++i) { mt[i] = s; s = 1812433253u * (s ^ (s >> 30)) + (unsigned)i + 1u; }
        mti = 624;
    }
    auto next32 = [&]() -> unsigned {
        if (mti >= 624) {
            for (int i = 0; i < 624; ++i) {
                unsigned y = (mt[i] & 0x80000000u) | (mt[(i + 1) % 624] & 0x7fffffffu);
                unsigned v = mt[(i + 397) % 624] ^ (y >> 1);
                if (y & 1u) v ^= 0x9908b0dfu;
                mt[i] = v;
            }
            mti = 0;
        }
        unsigned y = mt[mti++];
        y ^= y >> 11; y ^= (y << 7) & 0x9d2c5680u; y ^= (y << 15) & 0xefc60000u; y ^= y >> 18;
        return y;
    };
    auto rand_interval = [&](unsigned maxv) -> unsigned {
        if (maxv == 0u) return 0u;
        unsigned mask = maxv;
        mask |= mask >> 1; mask |= mask >> 2; mask |= mask >> 4; mask |= mask >> 8; mask |= mask >> 16;
        unsigned v;
        do { v = next32() & mask; } while (v > maxv);
        return v;
    };
    unsigned bm[NB];
    bm[0] = 0xffffffffu;
    for (int qb = 1; qb < NB; ++qb) {
        unsigned m = 1u;
        int lo = qb - 3; if (lo < 0) lo = 0;
        int hi = qb + 3; if (hi > NB - 1) hi = NB - 1;
        for (int kb = lo; kb <= hi; ++kb) m |= (1u << kb);
        bm[qb] = m;
    }
    for (int b = 1; b < NB; ++b) {
        int avail[NB]; int pop = 0;
        for (int x = 1; x < NB; ++x)
            if ((x - b > 3) || (b - x > 3)) avail[pop++] = x;
        if (pop == 0) continue;
        int perm[NB];
        for (int i = 0; i < pop; ++i) perm[i] = i;
        for (int i = pop - 1; i > 0; --i) {
            unsigned j = rand_interval((unsigned)i);
            int tmp = perm[i]; perm[i] = perm[j]; perm[j] = tmp;
        }
        int take = pop < 3 ? pop : 3;
        for (int tsel = 0; tsel < take; ++tsel) bm[b] |= (1u << avail[perm[tsel]]);
    }
    for (int i = 0; i < NB; ++i) g_blockmask[i] = bm[i];
}

// ---------------- fp32 -> bf16 hi/lo split (vectorized) ----------------
__global__ void split_f32(const float4* __restrict__ src,
                          __nv_bfloat16* __restrict__ h, __nv_bfloat16* __restrict__ l, int n4)
{
    int i = blockIdx.x * blockDim.x + threadIdx.x;
    if (i >= n4) return;
    float4 v = src[i];
    u32 h0, l0, h1, l1;
    split_pair(v.x, v.y, h0, l0);
    split_pair(v.z, v.w, h1, l1);
    u32* hp = (u32*)h + 2 * i;
    u32* lp = (u32*)l + 2 * i;
    hp[0] = h0; hp[1] = h1;
    lp[0] = l0; lp[1] = l1;
}

// ---------------- bf16-split GEMM: C[M,N] = A[M,K] @ W[N,K]^T + bias ----------------
// BM=128 BN=128 BK=32, 256 threads (8 warps, 2x4), warp tile 64x32, acc fp32.
__global__ __launch_bounds__(256) void gemm_bs(
    const __nv_bfloat16* __restrict__ Ah, const __nv_bfloat16* __restrict__ Al,
    const __nv_bfloat16* __restrict__ Wh, const __nv_bfloat16* __restrict__ Wl,
    const float* __restrict__ bias,
    __nv_bfloat16* __restrict__ Ch, __nv_bfloat16* __restrict__ Cl,
    float* __restrict__ Cf, int splitOut, int M, int N, int K)
{
    extern __shared__ char smraw[];
    const u32 sbase = smem_u32(smraw);
    const int t = threadIdx.x;
    const int lane = t & 31, warp = t >> 5;
    const int wy = warp >> 2, wx = warp & 3;
    const int m0 = blockIdx.y * 128, n0 = blockIdx.x * 128;
    const int KT = K / 32;

    // cp.async mapping: per matrix, thread handles chunks (r0,c) and (r0+64,c)
    const int cch = t & 3;
    const int r0 = t >> 2;
    const u32 d0 = swzG((u32)(r0 * 64 + cch * 16));
    const u32 d1 = swzG((u32)((r0 + 64) * 64 + cch * 16));
    const char* pAh0 = (const char*)(Ah + (size_t)(m0 + r0) * K) + cch * 16;
    const char* pAh1 = (const char*)(Ah + (size_t)(m0 + r0 + 64) * K) + cch * 16;
    const char* pAl0 = (const char*)(Al + (size_t)(m0 + r0) * K) + cch * 16;
    const char* pAl1 = (const char*)(Al + (size_t)(m0 + r0 + 64) * K) + cch * 16;
    const char* pWh0 = (const char*)(Wh + (size_t)(n0 + r0) * K) + cch * 16;
    const char* pWh1 = (const char*)(Wh + (size_t)(n0 + r0 + 64) * K) + cch * 16;
    const char* pWl0 = (const char*)(Wl + (size_t)(n0 + r0) * K) + cch * 16;
    const char* pWl1 = (const char*)(Wl + (size_t)(n0 + r0 + 64) * K) + cch * 16;

    // fragment ldmatrix offsets
    const int lr = lane & 15, lc = lane >> 4;
    u32 offA[4][2], offB[2][2];
#pragma unroll
    for (int i = 0; i < 4; ++i)
#pragma unroll
        for (int s = 0; s < 2; ++s)
            offA[i][s] = swzG((u32)((64 * wy + 16 * i + lr) * 64 + (2 * s + lc) * 16));
#pragma unroll
    for (int jg = 0; jg < 2; ++jg)
#pragma unroll
        for (int s = 0; s < 2; ++s)
            offB[jg][s] = swzG((u32)((32 * wx + 16 * jg + lr) * 64 + (2 * s + lc) * 16));

    float acc[4][4][4];
#pragma unroll
    for (int i = 0; i < 4; ++i)
#pragma unroll
        for (int j = 0; j < 4; ++j)
#pragma unroll
            for (int r = 0; r < 4; ++r) acc[i][j][r] = 0.f;

    auto prefetch = [&](int st, int kt) {
        u32 b = sbase + st * 32768;
        size_t ko = (size_t)kt * 64;  // 32 bf16 = 64B
        cpa16(b + d0,         pAh0 + ko); cpa16(b + d1,         pAh1 + ko);
        cpa16(b + 8192 + d0,  pAl0 + ko); cpa16(b + 8192 + d1,  pAl1 + ko);
        cpa16(b + 16384 + d0, pWh0 + ko); cpa16(b + 16384 + d1, pWh1 + ko);
        cpa16(b + 24576 + d0, pWl0 + ko); cpa16(b + 24576 + d1, pWl1 + ko);
    };

    prefetch(0, 0); CP_COMMIT;

    for (int kt = 0; kt < KT; ++kt) {
        int cur = kt & 1;
        if (kt + 1 < KT) { prefetch(cur ^ 1, kt + 1); CP_COMMIT; CP_WAIT1; }
        else { CP_WAIT0; }
        __syncthreads();
        u32 base = sbase + cur * 32768;
#pragma unroll
        for (int s = 0; s < 2; ++s) {
            u32 ah[4][4], al_[4][4];
#pragma unroll
            for (int i = 0; i < 4; ++i) {
                ldsm4(ah[i], base + offA[i][s]);
                ldsm4(al_[i], base + 8192 + offA[i][s]);
            }
            u32 bh[2][4], bl_[2][4];
#pragma unroll
            for (int jg = 0; jg < 2; ++jg) {
                ldsm4(bh[jg], base + 16384 + offB[jg][s]);
                ldsm4(bl_[jg], base + 24576 + offB[jg][s]);
            }
#pragma unroll
            for (int i = 0; i < 4; ++i)
#pragma unroll
                for (int j = 0; j < 4; ++j) {
                    int jg = j >> 1, sel = j & 1;
                    u32 b0h = bh[jg][sel], b1h = bh[jg][sel + 2];
                    u32 b0l = bl_[jg][sel], b1l = bl_[jg][sel + 2];
                    mma16816(acc[i][j], ah[i], b0h, b1h);
                    mma16816(acc[i][j], ah[i], b0l, b1l);
                    mma16816(acc[i][j], al_[i], b0h, b1h);
                }
        }
        __syncthreads();
    }

    // epilogue
    const int g = lane >> 2, tg = lane & 3;
#pragma unroll
    for (int i = 0; i < 4; ++i) {
        int rA = m0 + 64 * wy + 16 * i + g;
        int rB = rA + 8;
#pragma unroll
        for (int j = 0; j < 4; ++j) {
            int col = n0 + 32 * wx + 8 * j + 2 * tg;
            float b0 = bias[col], b1 = bias[col + 1];
            float v0 = acc[i][j][0] + b0, v1 = acc[i][j][1] + b1;
            float v2 = acc[i][j][2] + b0, v3 = acc[i][j][3] + b1;
            if (splitOut) {
                u32 h, l;
                split_pair(v0, v1, h, l);
                *(u32*)(Ch + (size_t)rA * N + col) = h;
                *(u32*)(Cl + (size_t)rA * N + col) = l;
                split_pair(v2, v3, h, l);
                *(u32*)(Ch + (size_t)rB * N + col) = h;
                *(u32*)(Cl + (size_t)rB * N + col) = l;
            } else {
                float2 w0 = make_float2(v0, v1);
                float2 w1 = make_float2(v2, v3);
                *(float2*)(Cf + (size_t)rA * N + col) = w0;
                *(float2*)(Cf + (size_t)rB * N + col) = w1;
            }
        }
    }
}

// ---------------- block-sparse flash attention, bf16-split tensor core ----------------
// grid (qb=32, b*H=32), 128 threads (4 warps). warp = m16 row strip x full 64 cols.
__global__ __launch_bounds__(128) void attn_bs(
    const __nv_bfloat16* __restrict__ Qh, const __nv_bfloat16* __restrict__ Ql,
    const __nv_bfloat16* __restrict__ Kh, const __nv_bfloat16* __restrict__ Kl,
    const __nv_bfloat16* __restrict__ Vh, const __nv_bfloat16* __restrict__ Vl,
    __nv_bfloat16* __restrict__ Oh, __nv_bfloat16* __restrict__ Ol)
{
    extern __shared__ char smraw[];
    const u32 sb = smem_u32(smraw);
    const int t = threadIdx.x;
    const int lane = t & 31, warp = t >> 5;
    const int qb = blockIdx.x;
    const int b = blockIdx.y >> 4, h = blockIdx.y & 15;
    const size_t gbase = (size_t)b * SEQN * EMB + (size_t)h * HD;
    const int lr = lane & 15, lc = lane >> 4;
    const int g = lane >> 2, tg = lane & 3;

    // Q tile load (hi/lo): 1024 chunks of 16B over 128 threads
#pragma unroll
    for (int it = 0; it < 8; ++it) {
        int id = t + 128 * it;
        int mat = it >> 2;             // 0 = Qh, 1 = Ql
        int cid = id & 511;
        int row = cid >> 3, c = cid & 7;
        u32 dst = sb + mat * 8192 + swzA((u32)(row * 128 + c * 16));
        const __nv_bfloat16* srcb = mat ? Ql : Qh;
        const char* src = (const char*)(srcb + gbase + (size_t)(qb * 64 + row) * EMB) + c * 16;
        cpa16(dst, src);
    }

    const __nv_bfloat16* kvsrc[4] = { Kh, Kl, Vh, Vl };
    auto loadKV = [&](int buf, int kb) {
#pragma unroll
        for (int it = 0; it < 16; ++it) {
            int id = t + 128 * it;
            int mat = it >> 2;         // 0=Kh 1=Kl 2=Vh 3=Vl
            int cid = id & 511;
            int row = cid >> 3, c = cid & 7;
            u32 dst = sb + 16384 + buf * 32768 + mat * 8192 + swzA((u32)(row * 128 + c * 16));
            const char* src = (const char*)(kvsrc[mat] + gbase + (size_t)(kb * 64 + row) * EMB) + c * 16;
            cpa16(dst, src);
        }
    };

    unsigned rem = g_blockmask[qb];
    int kb = __ffs(rem) - 1; rem &= rem - 1;
    loadKV(0, kb); CP_COMMIT;

    u32 offQ[4];
#pragma unroll
    for (int c = 0; c < 4; ++c)
        offQ[c] = swzA((u32)((16 * warp + lr) * 128 + (2 * c + lc) * 16));

    u32 qh[4][4], ql_[4][4];
    float o[8][4];
#pragma unroll
    for (int nt = 0; nt < 8; ++nt)
#pragma unroll
        for (int r = 0; r < 4; ++r) o[nt][r] = 0.f;
    float mrow0 = -INFINITY, mrow1 = -INFINITY, lrow0 = 0.f, lrow1 = 0.f;

    bool qloaded = false;
    int buf = 0;

    while (kb >= 0) {
        int nxt = rem ? (__ffs(rem) - 1) : -1;
        if (nxt >= 0) { rem &= rem - 1; loadKV(buf ^ 1, nxt); CP_COMMIT; CP_WAIT1; }
        else { CP_WAIT0; }
        __syncthreads();

        if (!qloaded) {
            qloaded = true;
#pragma unroll
            for (int c = 0; c < 4; ++c) {
                ldsm4(qh[c], sb + offQ[c]);
                ldsm4(ql_[c], sb + 8192 + offQ[c]);
            }
        }

        u32 kvb = sb + 16384 + buf * 32768;

        // ---- S = Q K^T (bf16 split, fp32 acc) ----
        float s[8][4];
#pragma unroll
        for (int nt = 0; nt < 8; ++nt)
#pragma unroll
            for (int r = 0; r < 4; ++r) s[nt][r] = 0.f;
#pragma unroll
        for (int c = 0; c < 4; ++c) {
#pragma unroll
            for (int jg = 0; jg < 4; ++jg) {
                u32 off = swzA((u32)((16 * jg + lr) * 128 + (2 * c + lc) * 16));
                u32 kh4[4], kl4[4];
                ldsm4(kh4, kvb + off);
                ldsm4(kl4, kvb + 8192 + off);
#pragma unroll
                for (int sel = 0; sel < 2; ++sel) {
                    int nt = 2 * jg + sel;
                    mma16816(s[nt], qh[c], kh4[sel], kh4[sel + 2]);
                    mma16816(s[nt], qh[c], kl4[sel], kl4[sel + 2]);
                    mma16816(s[nt], ql_[c], kh4[sel], kh4[sel + 2]);
                }
            }
        }

        // ---- online softmax (rows g and g+8) ----
        float mx0 = -INFINITY, mx1 = -INFINITY;
#pragma unroll
        for (int nt = 0; nt < 8; ++nt) {
            s[nt][0] *= 0.125f; s[nt][1] *= 0.125f; s[nt][2] *= 0.125f; s[nt][3] *= 0.125f;
            mx0 = fmaxf(mx0, fmaxf(s[nt][0], s[nt][1]));
            mx1 = fmaxf(mx1, fmaxf(s[nt][2], s[nt][3]));
        }
        mx0 = fmaxf(mx0, __shfl_xor_sync(0xffffffffu, mx0, 1, 4));
        mx0 = fmaxf(mx0, __shfl_xor_sync(0xffffffffu, mx0, 2, 4));
        mx1 = fmaxf(mx1, __shfl_xor_sync(0xffffffffu, mx1, 1, 4));
        mx1 = fmaxf(mx1, __shfl_xor_sync(0xffffffffu, mx1, 2, 4));
        float mn0 = fmaxf(mrow0, mx0), mn1 = fmaxf(mrow1, mx1);
        float a0 = __expf(mrow0 - mn0), a1 = __expf(mrow1 - mn1);
        float sum0 = 0.f, sum1 = 0.f;
#pragma unroll
        for (int nt = 0; nt < 8; ++nt) {
            s[nt][0] = __expf(s[nt][0] - mn0); s[nt][1] = __expf(s[nt][1] - mn0);
            s[nt][2] = __expf(s[nt][2] - mn1); s[nt][3] = __expf(s[nt][3] - mn1);
            sum0 += s[nt][0] + s[nt][1];
            sum1 += s[nt][2] + s[nt][3];
        }
        sum0 += __shfl_xor_sync(0xffffffffu, sum0, 1, 4);
        sum0 += __shfl_xor_sync(0xffffffffu, sum0, 2, 4);
        sum1 += __shfl_xor_sync(0xffffffffu, sum1, 1, 4);
        sum1 += __shfl_xor_sync(0xffffffffu, sum1, 2, 4);
        lrow0 = lrow0 * a0 + sum0; lrow1 = lrow1 * a1 + sum1;
        mrow0 = mn0; mrow1 = mn1;
#pragma unroll
        for (int nt = 0; nt < 8; ++nt) {
            o[nt][0] *= a0; o[nt][1] *= a0; o[nt][2] *= a1; o[nt][3] *= a1;
        }

        // P fragments (split)
        u32 ph[8][2], pl[8][2];
#pragma unroll
        for (int nt = 0; nt < 8; ++nt) {
            split_pair(s[nt][0], s[nt][1], ph[nt][0], pl[nt][0]);
            split_pair(s[nt][2], s[nt][3], ph[nt][1], pl[nt][1]);
        }

        // ---- O += P V ----
#pragma unroll
        for (int c = 0; c < 4; ++c) {
            u32 aph[4] = { ph[2 * c][0], ph[2 * c][1], ph[2 * c + 1][0], ph[2 * c + 1][1] };
            u32 apl[4] = { pl[2 * c][0], pl[2 * c][1], pl[2 * c + 1][0], pl[2 * c + 1][1] };
#pragma unroll
            for (int jg = 0; jg < 4; ++jg) {
                u32 off = swzA((u32)((16 * c + lr) * 128 + (2 * jg + lc) * 16));
                u32 vh4[4], vl4[4];
                ldsm4t(vh4, kvb + 16384 + off);
                ldsm4t(vl4, kvb + 24576 + off);
#pragma unroll
                for (int sel = 0; sel < 2; ++sel) {
                    int nt = 2 * jg + sel;
                    mma16816(o[nt], aph, vh4[2 * sel], vh4[2 * sel + 1]);
                    mma16816(o[nt], aph, vl4[2 * sel], vl4[2 * sel + 1]);
                    mma16816(o[nt], apl, vh4[2 * sel], vh4[2 * sel + 1]);
                }
            }
        }

        __syncthreads();
        buf ^= 1;
        kb = nxt;
    }

    // ---- epilogue: O/l -> ctx hi/lo ----
    float inv0 = 1.f / lrow0, inv1 = 1.f / lrow1;
    int row0 = qb * 64 + 16 * warp + g;
    int row1 = row0 + 8;
#pragma unroll
    for (int nt = 0; nt < 8; ++nt) {
        int col = 8 * nt + 2 * tg;
        size_t i0 = gbase + (size_t)row0 * EMB + col;
        size_t i1 = gbase + (size_t)row1 * EMB + col;
        u32 hh, ll;
        split_pair(o[nt][0] * inv0, o[nt][1] * inv0, hh, ll);
        *(u32*)(Oh + i0) = hh; *(u32*)(Ol + i0) = ll;
        split_pair(o[nt][2] * inv1, o[nt][3] * inv1, hh, ll);
        *(u32*)(Oh + i1) = hh; *(u32*)(Ol + i1) = ll;
    }
}

// ---------------- launcher ----------------
extern "C" void kernel_launch(void* const* d_in, const int* in_sizes, int n_in,
                              void* d_out, int out_size)
{
    (void)in_sizes; (void)n_in; (void)out_size;
    const float* hs = (const float*)d_in[0];
    const float* wq = (const float*)d_in[1];
    const float* bq = (const float*)d_in[2];
    const float* wk = (const float*)d_in[3];
    const float* bk = (const float*)d_in[4];
    const float* wv = (const float*)d_in[5];
    const float* bv = (const float*)d_in[6];
    const float* wo = (const float*)d_in[7];
    const float* bo = (const float*)d_in[8];
    float* out = (float*)d_out;

    __nv_bfloat16 *hs_h, *hs_l, *wq_h, *wq_l, *wk_h, *wk_l, *wv_h, *wv_l, *wo_h, *wo_l;
    __nv_bfloat16 *q_h, *q_l, *k_h, *k_l, *v_h, *v_l, *c_h, *c_l;
    cudaGetSymbolAddress((void**)&hs_h, g_hs_h); cudaGetSymbolAddress((void**)&hs_l, g_hs_l);
    cudaGetSymbolAddress((void**)&wq_h, g_wq_h); cudaGetSymbolAddress((void**)&wq_l, g_wq_l);
    cudaGetSymbolAddress((void**)&wk_h, g_wk_h); cudaGetSymbolAddress((void**)&wk_l, g_wk_l);
    cudaGetSymbolAddress((void**)&wv_h, g_wv_h); cudaGetSymbolAddress((void**)&wv_l, g_wv_l);
    cudaGetSymbolAddress((void**)&wo_h, g_wo_h); cudaGetSymbolAddress((void**)&wo_l, g_wo_l);
    cudaGetSymbolAddress((void**)&q_h, g_q_h);   cudaGetSymbolAddress((void**)&q_l, g_q_l);
    cudaGetSymbolAddress((void**)&k_h, g_k_h);   cudaGetSymbolAddress((void**)&k_l, g_k_l);
    cudaGetSymbolAddress((void**)&v_h, g_v_h);   cudaGetSymbolAddress((void**)&v_l, g_v_l);
    cudaGetSymbolAddress((void**)&c_h, g_c_h);   cudaGetSymbolAddress((void**)&c_l, g_c_l);

    cudaFuncSetAttribute(gemm_bs, cudaFuncAttributeMaxDynamicSharedMemorySize, 65536);
    cudaFuncSetAttribute(attn_bs, cudaFuncAttributeMaxDynamicSharedMemorySize, 81920);

    init_mask_kernel<<<1, 1>>>();

    // splits
    {
        int n4hs = MROWS * EMB / 4;   // 1048576
        int n4w = EMB * EMB / 4;      // 262144
        split_f32<<<n4hs / 256, 256>>>((const float4*)hs, hs_h, hs_l, n4hs);
        split_f32<<<n4w / 256, 256>>>((const float4*)wq, wq_h, wq_l, n4w);
        split_f32<<<n4w / 256, 256>>>((const float4*)wk, wk_h, wk_l, n4w);
        split_f32<<<n4w / 256, 256>>>((const float4*)wv, wv_h, wv_l, n4w);
        split_f32<<<n4w / 256, 256>>>((const float4*)wo, wo_h, wo_l, n4w);
    }

    dim3 gg(EMB / 128, MROWS / 128); // (8, 32)
    gemm_bs<<<gg, 256, 65536>>>(hs_h, hs_l, wq_h, wq_l, bq, q_h, q_l, nullptr, 1, MROWS, EMB, EMB);
    gemm_bs<<<gg, 256, 65536>>>(hs_h, hs_l, wk_h, wk_l, bk, k_h, k_l, nullptr, 1, MROWS, EMB, EMB);
    gemm_bs<<<gg, 256, 65536>>>(hs_h, hs_l, wv_h, wv_l, bv, v_h, v_l, nullptr, 1, MROWS, EMB, EMB);

    attn_bs<<<dim3(NB, BATCH * NH), 128, 81920>>>(q_h, q_l, k_h, k_l, v_h, v_l, c_h, c_l);

    gemm_bs<<<gg, 256, 65536>>>(c_h, c_l, wo_h, wo_l, bo, nullptr, nullptr, out, 0, MROWS, EMB, EMB);
}